// round 12
// baseline (speedup 1.0000x reference)
#include <cuda_runtime.h>
#include <cuda_bf16.h>

// DensityLoss: out[b,y,x] = loss[b,y,x] * (fg ? 10 : 1) / (H*W*B),  1/(H*W*B)=2^-23 exact.
// fg = pixel covered by >=1 of 64 boxes (half-open [y1:y2, x1:x2)).
//
// Round 12: full async-proxy streaming. One 16KB cp.async.bulk LOAD per CTA
// (4 contiguous rows), per-warp bitmap build overlapped with the transfer,
// consume scales the tile IN PLACE in smem (LDS.128 -> FMUL -> STS.128), and
// each row leaves via one 4KB cp.async.bulk STORE (async proxy, bypasses the
// L1tex global-store path, which was the highest counter at 42%). Global
// traffic now rides the TMA path in both directions; the L1 LSU carries only
// on-chip LDS/STS.

#define B_DIM 8
#define H_DIM 1024
#define W_DIM 1024
#define N_BOX 64
#define THREADS 128
#define RPC 4                         // rows per CTA (one warp per row)
#define ROW_BYTES (W_DIM * 4)         // 4096
#define TILE_BYTES (RPC * ROW_BYTES)  // 16384 (rows are contiguous in gmem)

__global__ __launch_bounds__(THREADS)
void density_loss_kernel(const float* __restrict__ loss,
                         const int4* __restrict__ bboxes,   // [B, N] (x1,y1,x2,y2)
                         float* __restrict__ out)
{
    __shared__ __align__(16) float4 tile[RPC][W_DIM / 4];        // 16 KB
    __shared__ unsigned bm[RPC][W_DIM / 32];                     // 512 B
    __shared__ __align__(8) unsigned long long mbar;

    const int t    = threadIdx.x;
    const int lane = t & 31;
    const int w    = t >> 5;                    // warp id == row within CTA
    const int row  = (blockIdx.x << 2) + w;     // b*H + y
    const int b    = row >> 10;
    const int y    = row & (H_DIM - 1);

    const unsigned mb = (unsigned)__cvta_generic_to_shared(&mbar);

    // ---- thread 0: init barrier, then ONE 16KB bulk load (4 contiguous rows)
    if (t == 0) {
        asm volatile("mbarrier.init.shared.b64 [%0], %1;" :: "r"(mb), "r"(1) : "memory");
        asm volatile("mbarrier.arrive.expect_tx.shared.b64 _, [%0], %1;"
                     :: "r"(mb), "r"(TILE_BYTES) : "memory");
        unsigned dst = (unsigned)__cvta_generic_to_shared(&tile[0][0]);
        const float* src = loss + ((size_t)(blockIdx.x) << 12);
        asm volatile("cp.async.bulk.shared::cta.global.mbarrier::complete_tx::bytes "
                     "[%0], [%1], %2, [%3];"
                     :: "r"(dst), "l"(src), "r"(TILE_BYTES), "r"(mb) : "memory");
    }

    // ---- build this row's coverage bitmap (overlaps the bulk copy) ----
    bm[w][lane] = 0u;
    const int4* bb = bboxes + (b << 6);
    const int4 b0 = bb[lane];
    const int4 b1 = bb[lane + 32];
    __syncwarp();

    #pragma unroll
    for (int k = 0; k < 2; k++) {
        const int4 bx = k ? b1 : b0;
        const int x1 = min(max(bx.x, 0), W_DIM);
        const int y1 = min(max(bx.y, 0), H_DIM);
        const int x2 = min(max(bx.z, 0), W_DIM);
        const int y2 = min(max(bx.w, 0), H_DIM);
        if (y >= y1 && y < y2 && x1 < x2) {
            const int wA = x1 >> 5;
            const int wB = (x2 - 1) >> 5;
            const unsigned mA = 0xffffffffu << (x1 & 31);
            const unsigned mB = 0xffffffffu >> (31 - ((x2 - 1) & 31));
            if (wA == wB) {
                atomicOr(&bm[w][wA], mA & mB);
            } else {
                atomicOr(&bm[w][wA], mA);
                atomicOr(&bm[w][wB], mB);
                for (int q = wA + 1; q < wB; q++)
                    bm[w][q] = 0xffffffffu;     // same-value race: benign
            }
        }
    }

    // ---- make mbarrier init visible to all warps, then wait for the tile ----
    __syncthreads();
    asm volatile(
        "{\n\t"
        ".reg .pred P;\n\t"
        "WAIT_%=:\n\t"
        "mbarrier.try_wait.parity.acquire.cta.shared::cta.b64 P, [%0], 0, 0x989680;\n\t"
        "@P bra DONE_%=;\n\t"
        "bra WAIT_%=;\n\t"
        "DONE_%=:\n\t"
        "}"
        :: "r"(mb) : "memory");

    // ---- scale the tile IN PLACE: LDS.128 -> weight -> STS.128 ----
    const float INV = 1.0f / 8388608.0f;   // 2^-23, exact
    const float WFG = 10.0f * INV;
    const int shift = (lane & 7) << 2;

    #pragma unroll
    for (int q = 0; q < 8; q++) {
        const float4   l4  = tile[w][(q << 5) + lane];
        const unsigned nib = bm[w][(q << 2) + (lane >> 3)] >> shift;
        float4 o;
        o.x = l4.x * ((nib & 1u) ? WFG : INV);
        o.y = l4.y * ((nib & 2u) ? WFG : INV);
        o.z = l4.z * ((nib & 4u) ? WFG : INV);
        o.w = l4.w * ((nib & 8u) ? WFG : INV);
        tile[w][(q << 5) + lane] = o;
    }

    // ---- order generic STS before async-proxy read, then bulk store the row
    asm volatile("fence.proxy.async.shared::cta;" ::: "memory");
    __syncwarp();

    if (lane == 0) {
        unsigned src = (unsigned)__cvta_generic_to_shared(&tile[w][0]);
        float* dst = out + ((size_t)row << 10);
        asm volatile("cp.async.bulk.global.shared::cta.bulk_group [%0], [%1], %2;"
                     :: "l"(dst), "r"(src), "r"(ROW_BYTES) : "memory");
        asm volatile("cp.async.bulk.commit_group;" ::: "memory");
        asm volatile("cp.async.bulk.wait_group 0;" ::: "memory");
    }
}

extern "C" void kernel_launch(void* const* d_in, const int* in_sizes, int n_in,
                              void* d_out, int out_size)
{
    const float* loss   = (const float*)d_in[0];
    // d_in[1] = pred_densities: unused by the reference computation.
    const int4*  bboxes = (const int4*)d_in[2];
    float*       out    = (float*)d_out;

    density_loss_kernel<<<(B_DIM * H_DIM) / RPC, THREADS>>>(loss, bboxes, out);
}

// round 14
// speedup vs baseline: 1.0200x; 1.0200x over previous
#include <cuda_runtime.h>
#include <cuda_bf16.h>

// DensityLoss: out[b,y,x] = loss[b,y,x] * (fg ? 10 : 1) / (H*W*B),  1/(H*W*B)=2^-23 exact.
// fg = pixel covered by >=1 of 64 boxes (half-open [y1:y2, x1:x2)).
//
// Round 13: per-warp double-buffered TMA pipeline. All previous designs ran
// load-phase -> store-phase per CTA with the whole grid resident in one wave,
// so chip-wide the 32MB read stream and 32MB write stream were SERIALIZED
// (5.7us + 5.7us = the 11.4us plateau). Here each warp owns 4 rows and a
// 2 x 4KB ring: while row i is being scaled+bulk-stored, row i+1's bulk load
// is in flight -> reads and writes overlap chip-wide. Warp-private barriers,
// no CTA syncs.

#define B_DIM 8
#define H_DIM 1024
#define W_DIM 1024
#define N_BOX 64
#define THREADS 128
#define WARPS 4
#define RPW 4                              // rows per warp
#define ROWS_PER_CTA (WARPS * RPW)         // 16
#define ROW_BYTES (W_DIM * 4)              // 4096
#define GRID ((B_DIM * H_DIM) / ROWS_PER_CTA)   // 512

__global__ __launch_bounds__(THREADS)
void density_loss_kernel(const float* __restrict__ loss,
                         const int4* __restrict__ bboxes,   // [B, N] (x1,y1,x2,y2)
                         float* __restrict__ out)
{
    __shared__ __align__(16) float4 buf[WARPS][2][W_DIM / 4];     // 32 KB
    __shared__ unsigned bm[WARPS][W_DIM / 32];                    // 512 B
    __shared__ __align__(8) unsigned long long mbar[WARPS][2];

    const int t    = threadIdx.x;
    const int lane = t & 31;
    const int w    = t >> 5;
    const int row0 = blockIdx.x * ROWS_PER_CTA + w * RPW;   // 4 consecutive rows
    const int b    = row0 >> 10;
    const int y0   = row0 & (H_DIM - 1);                    // y0 + i never wraps (16-aligned)

    const unsigned mb0 = (unsigned)__cvta_generic_to_shared(&mbar[w][0]);
    const unsigned mb1 = (unsigned)__cvta_generic_to_shared(&mbar[w][1]);

    // ---- warp-private init ----
    if (lane < 2) {
        unsigned m = lane ? mb1 : mb0;
        asm volatile("mbarrier.init.shared.b64 [%0], 1;" :: "r"(m) : "memory");
    }
    const int4* bb = bboxes + (b << 6);
    const int4 bx0 = bb[lane];
    const int4 bx1 = bb[lane + 32];
    __syncwarp();

    // ---- prime: bulk load row 0 into stage 0 ----
    if (lane == 0) {
        unsigned dst = (unsigned)__cvta_generic_to_shared(&buf[w][0][0]);
        asm volatile("mbarrier.arrive.expect_tx.shared.b64 _, [%0], %1;"
                     :: "r"(mb0), "r"(ROW_BYTES) : "memory");
        asm volatile("cp.async.bulk.shared::cta.global.mbarrier::complete_tx::bytes "
                     "[%0], [%1], %2, [%3];"
                     :: "r"(dst), "l"(loss + ((size_t)row0 << 10)), "r"(ROW_BYTES), "r"(mb0)
                     : "memory");
    }

    const float INV = 1.0f / 8388608.0f;   // 2^-23, exact
    const float WFG = 10.0f * INV;
    const int shift = (lane & 7) << 2;

    #pragma unroll
    for (int i = 0; i < RPW; i++) {
        const int      stage = i & 1;
        const unsigned mb    = stage ? mb1 : mb0;

        // ---- issue next row's load (double buffer, WAR-guarded) ----
        if (i + 1 < RPW && lane == 0) {
            if (i >= 1)   // store i-1 read buf[(i+1)&1]; wait until its smem reads done
                asm volatile("cp.async.bulk.wait_group.read 0;" ::: "memory");
            const unsigned nmb = stage ? mb0 : mb1;
            unsigned dst = (unsigned)__cvta_generic_to_shared(&buf[w][(i + 1) & 1][0]);
            asm volatile("mbarrier.arrive.expect_tx.shared.b64 _, [%0], %1;"
                         :: "r"(nmb), "r"(ROW_BYTES) : "memory");
            asm volatile("cp.async.bulk.shared::cta.global.mbarrier::complete_tx::bytes "
                         "[%0], [%1], %2, [%3];"
                         :: "r"(dst), "l"(loss + ((size_t)(row0 + i + 1) << 10)),
                            "r"(ROW_BYTES), "r"(nmb)
                         : "memory");
        }

        // ---- build row i's coverage bitmap (overlaps the in-flight load) ----
        __syncwarp();                 // prior iteration's bm reads complete
        bm[w][lane] = 0u;
        __syncwarp();
        const int y = y0 + i;
        #pragma unroll
        for (int k = 0; k < 2; k++) {
            const int4 bx = k ? bx1 : bx0;
            const int x1 = min(max(bx.x, 0), W_DIM);
            const int y1 = min(max(bx.y, 0), H_DIM);
            const int x2 = min(max(bx.z, 0), W_DIM);
            const int y2 = min(max(bx.w, 0), H_DIM);
            if (y >= y1 && y < y2 && x1 < x2) {
                const int wA = x1 >> 5;
                const int wB = (x2 - 1) >> 5;
                const unsigned mA = 0xffffffffu << (x1 & 31);
                const unsigned mB = 0xffffffffu >> (31 - ((x2 - 1) & 31));
                if (wA == wB) {
                    atomicOr(&bm[w][wA], mA & mB);
                } else {
                    atomicOr(&bm[w][wA], mA);
                    atomicOr(&bm[w][wB], mB);
                    for (int q = wA + 1; q < wB; q++)
                        bm[w][q] = 0xffffffffu;     // same-value race: benign
                }
            }
        }
        __syncwarp();

        // ---- wait for row i's data (acquire orders the ld.shared below) ----
        const unsigned parity = (i >> 1) & 1;
        asm volatile(
            "{\n\t"
            ".reg .pred P;\n\t"
            "WAIT_%=:\n\t"
            "mbarrier.try_wait.parity.acquire.cta.shared::cta.b64 P, [%0], %1, 0x989680;\n\t"
            "@P bra DONE_%=;\n\t"
            "bra WAIT_%=;\n\t"
            "DONE_%=:\n\t"
            "}"
            :: "r"(mb), "r"(parity) : "memory");

        // ---- scale in place: LDS.128 -> weight -> STS.128 ----
        #pragma unroll
        for (int q = 0; q < 8; q++) {
            const float4   l4  = buf[w][stage][(q << 5) + lane];
            const unsigned nib = bm[w][(q << 2) + (lane >> 3)] >> shift;
            float4 o;
            o.x = l4.x * ((nib & 1u) ? WFG : INV);
            o.y = l4.y * ((nib & 2u) ? WFG : INV);
            o.z = l4.z * ((nib & 4u) ? WFG : INV);
            o.w = l4.w * ((nib & 8u) ? WFG : INV);
            buf[w][stage][(q << 5) + lane] = o;
        }

        // ---- order STS before async-proxy read, then bulk store row i ----
        asm volatile("fence.proxy.async.shared::cta;" ::: "memory");
        __syncwarp();
        if (lane == 0) {
            unsigned src = (unsigned)__cvta_generic_to_shared(&buf[w][stage][0]);
            asm volatile("cp.async.bulk.global.shared::cta.bulk_group [%0], [%1], %2;"
                         :: "l"(out + ((size_t)(row0 + i) << 10)), "r"(src), "r"(ROW_BYTES)
                         : "memory");
            asm volatile("cp.async.bulk.commit_group;" ::: "memory");
        }
    }

    // ---- drain outstanding bulk stores before exit ----
    if (lane == 0)
        asm volatile("cp.async.bulk.wait_group 0;" ::: "memory");
}

extern "C" void kernel_launch(void* const* d_in, const int* in_sizes, int n_in,
                              void* d_out, int out_size)
{
    const float* loss   = (const float*)d_in[0];
    // d_in[1] = pred_densities: unused by the reference computation.
    const int4*  bboxes = (const int4*)d_in[2];
    float*       out    = (float*)d_out;

    density_loss_kernel<<<GRID, THREADS>>>(loss, bboxes, out);
}

// round 16
// speedup vs baseline: 1.0226x; 1.0025x over previous
#include <cuda_runtime.h>
#include <cuda_bf16.h>

// DensityLoss: out[b,y,x] = loss[b,y,x] * (fg ? 10 : 1) / (H*W*B),  1/(H*W*B)=2^-23 exact.
// fg = pixel covered by >=1 of 64 boxes (half-open [y1:y2, x1:x2)).
//
// Final shape. Evidence across 6 designs (occ 19-80%, issue 16-37%, LDG/STG/
// TMA/pipelined) shows duration pinned at ~11.4us with frozen memory counters:
// the kernel sits at the path-independent LTS byte-rate cap (~5.6 TB/s
// realized) moving its compulsory 64 MB. This revision only trims tails:
// one 32KB cp.async.bulk load per 256-thread CTA (halves TMA/mbarrier ops),
// per-warp bitmap build overlapped with the transfer, direct STG.128 consume
// (all lanes, no second smem pass), and st.global.cs on the output so the
// streaming writes don't evict the L2-resident input between graph replays.

#define B_DIM 8
#define H_DIM 1024
#define W_DIM 1024
#define N_BOX 64
#define THREADS 256
#define RPC 8                          // rows per CTA, one warp per row
#define ROW_BYTES (W_DIM * 4)          // 4096
#define TILE_BYTES (RPC * ROW_BYTES)   // 32768 (rows contiguous in gmem)
#define GRID ((B_DIM * H_DIM) / RPC)   // 1024

__global__ __launch_bounds__(THREADS)
void density_loss_kernel(const float* __restrict__ loss,
                         const int4* __restrict__ bboxes,   // [B, N] (x1,y1,x2,y2)
                         float* __restrict__ out)
{
    __shared__ __align__(16) float4 tile[RPC][W_DIM / 4];        // 32 KB
    __shared__ unsigned bm[RPC][W_DIM / 32];                     // 1 KB
    __shared__ __align__(8) unsigned long long mbar;

    const int t    = threadIdx.x;
    const int lane = t & 31;
    const int w    = t >> 5;                    // warp id == row within CTA
    const int row  = (blockIdx.x << 3) + w;     // b*H + y (8 rows share one b)
    const int b    = row >> 10;
    const int y    = row & (H_DIM - 1);

    const unsigned mb = (unsigned)__cvta_generic_to_shared(&mbar);

    // ---- thread 0: init barrier + ONE 32KB bulk load (8 contiguous rows) ----
    if (t == 0) {
        asm volatile("mbarrier.init.shared.b64 [%0], 1;" :: "r"(mb) : "memory");
        asm volatile("mbarrier.arrive.expect_tx.shared.b64 _, [%0], %1;"
                     :: "r"(mb), "r"(TILE_BYTES) : "memory");
        unsigned dst = (unsigned)__cvta_generic_to_shared(&tile[0][0]);
        const float* src = loss + ((size_t)blockIdx.x << 13);
        asm volatile("cp.async.bulk.shared::cta.global.mbarrier::complete_tx::bytes "
                     "[%0], [%1], %2, [%3];"
                     :: "r"(dst), "l"(src), "r"(TILE_BYTES), "r"(mb) : "memory");
    }

    // ---- build this row's coverage bitmap (overlaps the bulk copy) ----
    bm[w][lane] = 0u;
    const int4* bb = bboxes + (b << 6);
    const int4 b0 = bb[lane];
    const int4 b1 = bb[lane + 32];
    __syncwarp();

    #pragma unroll
    for (int k = 0; k < 2; k++) {
        const int4 bx = k ? b1 : b0;
        const int x1 = min(max(bx.x, 0), W_DIM);
        const int y1 = min(max(bx.y, 0), H_DIM);
        const int x2 = min(max(bx.z, 0), W_DIM);
        const int y2 = min(max(bx.w, 0), H_DIM);
        if (y >= y1 && y < y2 && x1 < x2) {
            const int wA = x1 >> 5;
            const int wB = (x2 - 1) >> 5;
            const unsigned mA = 0xffffffffu << (x1 & 31);
            const unsigned mB = 0xffffffffu >> (31 - ((x2 - 1) & 31));
            if (wA == wB) {
                atomicOr(&bm[w][wA], mA & mB);
            } else {
                atomicOr(&bm[w][wA], mA);
                atomicOr(&bm[w][wB], mB);
                for (int q = wA + 1; q < wB; q++)
                    bm[w][q] = 0xffffffffu;     // same-value race: benign
            }
        }
    }

    // ---- publish mbarrier init to all warps, then wait for the tile ----
    __syncthreads();
    asm volatile(
        "{\n\t"
        ".reg .pred P;\n\t"
        "WAIT_%=:\n\t"
        "mbarrier.try_wait.parity.acquire.cta.shared::cta.b64 P, [%0], 0, 0x989680;\n\t"
        "@P bra DONE_%=;\n\t"
        "bra WAIT_%=;\n\t"
        "DONE_%=:\n\t"
        "}"
        :: "r"(mb) : "memory");

    // ---- consume: LDS.128 -> weight -> STG.128 (.cs: evict-first output) ----
    const float INV = 1.0f / 8388608.0f;   // 2^-23, exact
    const float WFG = 10.0f * INV;
    const int shift = (lane & 7) << 2;

    float4* op = reinterpret_cast<float4*>(out + ((size_t)row << 10)) + lane;

    #pragma unroll
    for (int q = 0; q < 8; q++) {
        const float4   l4  = tile[w][(q << 5) + lane];
        const unsigned nib = bm[w][(q << 2) + (lane >> 3)] >> shift;
        float4 o;
        o.x = l4.x * ((nib & 1u) ? WFG : INV);
        o.y = l4.y * ((nib & 2u) ? WFG : INV);
        o.z = l4.z * ((nib & 4u) ? WFG : INV);
        o.w = l4.w * ((nib & 8u) ? WFG : INV);
        __stcs(op + (q << 5), o);
    }
}

extern "C" void kernel_launch(void* const* d_in, const int* in_sizes, int n_in,
                              void* d_out, int out_size)
{
    const float* loss   = (const float*)d_in[0];
    // d_in[1] = pred_densities: unused by the reference computation.
    const int4*  bboxes = (const int4*)d_in[2];
    float*       out    = (float*)d_out;

    density_loss_kernel<<<GRID, THREADS>>>(loss, bboxes, out);
}